// round 2
// baseline (speedup 1.0000x reference)
#include <cuda_runtime.h>

typedef unsigned long long ull;

#define M_    8
#define K_    256
#define DG_   128
#define D_    1024
#define HW_   1024
#define NPIX_ 32768

#define QUANT_ELEMS (33554432)
#define CODE_ELEMS  (262144)

#define GAP_THRESH 1e-3f
#define REF_WIN    2e-3f
#define CAP_       32768

// Scratch (__device__ globals per allocation rules)
__device__ float g_E[M_ * DG_ * K_];     // [m][d][k]
__device__ float g_V[M_ * K_ * DG_];     // [m][k][d]
__device__ float g_KPH[M_ * K_ * DG_];   // kproj hi [m][k][c]
__device__ float g_KPL[M_ * K_ * DG_];   // kproj lo
__device__ int   g_count;
__device__ int   g_list[CAP_];

// ---------------- packed f32x2 helpers ----------------
__device__ __forceinline__ ull pack2(float x, float y) {
    ull r; asm("mov.b64 %0, {%1,%2};" : "=l"(r) : "f"(x), "f"(y)); return r;
}
__device__ __forceinline__ void unpack2(ull v, float &x, float &y) {
    asm("mov.b64 {%0,%1}, %2;" : "=f"(x), "=f"(y) : "l"(v));
}
__device__ __forceinline__ ull fma2_(ull a, ull b, ull c) {
    ull d; asm("fma.rn.f32x2 %0, %1, %2, %3;" : "=l"(d) : "l"(a), "l"(b), "l"(c));
    return d;
}

// ---------------- double-float (Dekker) helpers: fast-math safe ----------------
struct dd { float h, l; };

__device__ __forceinline__ dd two_sum(float a, float b) {
    float s  = __fadd_rn(a, b);
    float bb = __fsub_rn(s, a);
    float e  = __fadd_rn(__fsub_rn(a, __fsub_rn(s, bb)), __fsub_rn(b, bb));
    dd r; r.h = s; r.l = e; return r;
}
__device__ __forceinline__ dd two_prod(float a, float b) {
    float p = __fmul_rn(a, b);
    float e = __fmaf_rn(a, b, -p);
    dd r; r.h = p; r.l = e; return r;
}
__device__ __forceinline__ dd dd_add(dd x, dd y) {
    dd s = two_sum(x.h, y.h);
    float lo = __fadd_rn(__fadd_rn(x.l, y.l), s.l);
    float hi = __fadd_rn(s.h, lo);
    float l  = __fadd_rn(__fsub_rn(s.h, hi), lo);
    dd r; r.h = hi; r.l = l; return r;
}
__device__ __forceinline__ dd dd_fma(dd acc, float a, float b) {
    return dd_add(acc, two_prod(a, b));
}
__device__ __forceinline__ dd dd_mul(dd x, dd y) {
    dd p = two_prod(x.h, y.h);
    float t = __fmaf_rn(x.h, y.l, p.l);
    t = __fmaf_rn(x.l, y.h, t);
    float hi = __fadd_rn(p.h, t);
    float l  = __fadd_rn(__fsub_rn(p.h, hi), t);
    dd r; r.h = hi; r.l = l; return r;
}

// ---------------------------------------------------------------------------
// Precompute: E[m][d][k] (fp32 fast path), V[m][k][d], kproj dd pair.
// grid (K_, M_), 128 threads. Also resets the refine-list counter.
// ---------------------------------------------------------------------------
__global__ void precompute_kernel(const float* __restrict__ codebook,
                                  const float* __restrict__ wq,
                                  const float* __restrict__ wk,
                                  const float* __restrict__ wv) {
    __shared__ float cb[DG_];
    __shared__ float kp[DG_];
    int m = blockIdx.y, k = blockIdx.x, t = threadIdx.x;

    if (m == 0 && k == 0 && t == 0) g_count = 0;

    cb[t] = codebook[((size_t)m * K_ + k) * DG_ + t];
    __syncthreads();

    // thread t == output channel c: kproj[c] (dd), vproj[c] (fp32)
    const float* wkr = wk + ((size_t)m * DG_ + t) * DG_;
    const float* wvr = wv + ((size_t)m * DG_ + t) * DG_;
    dd sk; sk.h = 0.f; sk.l = 0.f;
    float sv = 0.f;
#pragma unroll 4
    for (int d = 0; d < DG_; d++) {
        float c = cb[d];
        sk = dd_fma(sk, c, wkr[d]);
        sv = fmaf(c, wvr[d], sv);
    }
    size_t kbase = ((size_t)m * K_ + k) * DG_ + t;
    g_KPH[kbase] = sk.h;
    g_KPL[kbase] = sk.l;
    g_V[kbase]   = sv;
    kp[t] = sk.h;
    __syncthreads();

    // thread t == d: E[m][d][k] = sum_c kp[c] * wq[m][c][d]
    const float* wqm = wq + (size_t)m * DG_ * DG_;
    float e = 0.f;
#pragma unroll 8
    for (int c = 0; c < DG_; c++) e = fmaf(kp[c], wqm[c * DG_ + t], e);
    g_E[((size_t)m * DG_ + t) * K_ + k] = e;
}

// ---------------------------------------------------------------------------
// Main kernel: block = 256 threads, tile = 64 pixels x 256 k, fixed m.
// grid (NPIX_/64 = 512, M_ = 8)
// ---------------------------------------------------------------------------
#define PIX  64
#define DCH  16
#define KCH  32

#define SM_QS    0
#define SM_ES    1024
#define SM_SS    5120
#define SM_RINV  (5120 + 16448)
#define SM_VS    (5120 + 16448 + 64)
#define SM_FLOATS (5120 + 16448 + 64 + 4096)
#define SMEM_BYTES (SM_FLOATS * 4)

__global__ void __launch_bounds__(256, 2)
main_kernel(const float* __restrict__ latent,
            const float* __restrict__ unif,
            float* __restrict__ quant_out,
            float* __restrict__ code_out,
            float* __restrict__ logit_out) {
    extern __shared__ float sm[];
    float* Qs    = sm + SM_QS;
    float* Es    = sm + SM_ES;
    float* Ss    = sm + SM_SS;
    float* rinvs = sm + SM_RINV;
    float* Vs    = sm + SM_VS;

    const int m  = blockIdx.y;
    const int p0 = blockIdx.x * PIX;
    const int n  = p0 >> 10;
    const int s0 = p0 & 1023;
    const int tid = threadIdx.x;
    const int kt  = tid & 31;
    const int pt  = tid >> 5;

    const float* latb = latent + ((size_t)n * D_ + (size_t)m * DG_) * HW_ + s0;
    const float* Em   = g_E + (size_t)m * DG_ * K_;

    // ---------------- Pass 1: logits ----------------
    ull acc[8][4];
#pragma unroll
    for (int i = 0; i < 8; i++)
#pragma unroll
        for (int jj = 0; jj < 4; jj++) acc[i][jj] = 0ull;

    for (int d0 = 0; d0 < DG_; d0 += DCH) {
#pragma unroll
        for (int r = 0; r < 4; r++) {
            int idx = tid + 256 * r;
            int dr = idx >> 6, cc = idx & 63;
            Qs[idx] = latb[(size_t)(d0 + dr) * HW_ + cc];
        }
#pragma unroll
        for (int r = 0; r < 16; r++) {
            int idx = tid + 256 * r;
            Es[idx] = Em[(size_t)d0 * K_ + idx];
        }
        __syncthreads();

#pragma unroll
        for (int d = 0; d < DCH; d++) {
            float4 e0 = *(const float4*)&Es[d * K_ + kt * 8];
            float4 e1 = *(const float4*)&Es[d * K_ + kt * 8 + 4];
            ull eb[4];
            eb[0] = pack2(e0.x, e0.y); eb[1] = pack2(e0.z, e0.w);
            eb[2] = pack2(e1.x, e1.y); eb[3] = pack2(e1.z, e1.w);
            float4 q0 = *(const float4*)&Qs[d * PIX + pt * 8];
            float4 q1 = *(const float4*)&Qs[d * PIX + pt * 8 + 4];
            float qv[8] = {q0.x, q0.y, q0.z, q0.w, q1.x, q1.y, q1.z, q1.w};
#pragma unroll
            for (int i = 0; i < 8; i++) {
                ull qd = pack2(qv[i], qv[i]);
#pragma unroll
                for (int jj = 0; jj < 4; jj++)
                    acc[i][jj] = fma2_(qd, eb[jj], acc[i][jj]);
            }
        }
        __syncthreads();
    }

    // ---------------- Epilogue ----------------
#pragma unroll 2
    for (int i = 0; i < 8; i++) {
        const int p = pt * 8 + i;
        const size_t pg = (size_t)(p0 + p);

        float l[8];
#pragma unroll
        for (int jj = 0; jj < 4; jj++) unpack2(acc[i][jj], l[2 * jj], l[2 * jj + 1]);

        float* lo = logit_out + (pg * M_ + m) * K_ + kt * 8;
        *(float4*)lo       = make_float4(l[0], l[1], l[2], l[3]);
        *(float4*)(lo + 4) = make_float4(l[4], l[5], l[6], l[7]);

        // top-2 of raw logits (first-index tie break on top-1)
        float b1 = l[0]; int i1 = kt * 8; float b2 = -3.4e38f;
#pragma unroll
        for (int j = 1; j < 8; j++) {
            if (l[j] > b1) { b2 = b1; b1 = l[j]; i1 = kt * 8 + j; }
            else if (l[j] > b2) b2 = l[j];
        }
#pragma unroll
        for (int o = 16; o > 0; o >>= 1) {
            float ob1 = __shfl_xor_sync(0xFFFFFFFFu, b1, o);
            int   oi1 = __shfl_xor_sync(0xFFFFFFFFu, i1, o);
            float ob2 = __shfl_xor_sync(0xFFFFFFFFu, b2, o);
            if (ob1 > b1 || (ob1 == b1 && oi1 < i1)) {
                b2 = fmaxf(b1, ob2); b1 = ob1; i1 = oi1;
            } else {
                b2 = fmaxf(b2, ob1);
            }
        }

        // gumbel: -log(-log u); inner log via log1pf to kill cancellation at u->1
        const float* up = unif + (pg * M_ + m) * K_ + kt * 8;
        float4 u0 = *(const float4*)up, u1 = *(const float4*)(up + 4);
        float uu[8] = {u0.x, u0.y, u0.z, u0.w, u1.x, u1.y, u1.z, u1.w};
        float t[8];
#pragma unroll
        for (int j = 0; j < 8; j++) {
            float nlu = -log1pf(__fsub_rn(uu[j], 1.0f));   // -log(u), accurate near 1
            t[j] = l[j] - __logf(nlu);
        }

        float tm = t[0];
#pragma unroll
        for (int j = 1; j < 8; j++) tm = fmaxf(tm, t[j]);
#pragma unroll
        for (int o = 16; o > 0; o >>= 1)
            tm = fmaxf(tm, __shfl_xor_sync(0xFFFFFFFFu, tm, o));

        float e[8], s = 0.f;
#pragma unroll
        for (int j = 0; j < 8; j++) { e[j] = __expf(t[j] - tm); s += e[j]; }
#pragma unroll
        for (int o = 16; o > 0; o >>= 1)
            s += __shfl_xor_sync(0xFFFFFFFFu, s, o);

#pragma unroll
        for (int j = 0; j < 8; j++) Ss[p * 257 + kt * 8 + j] = e[j];
        if (kt == 0) {
            rinvs[p] = 1.0f / s;
            code_out[pg * M_ + m] = (float)i1;
            if (b1 - b2 < GAP_THRESH) {
                int idx = atomicAdd(&g_count, 1);
                if (idx < CAP_) g_list[idx] = (int)(pg * M_ + m);
            }
        }
    }

    // ---------------- Pass 2: quantized ----------------
    const int pl    = tid & 63;
    const int dbase = (tid >> 6) * 32;

    ull qacc[16];
#pragma unroll
    for (int jj = 0; jj < 16; jj++) qacc[jj] = 0ull;

    const float* Vm = g_V + (size_t)m * K_ * DG_;
    for (int k0 = 0; k0 < K_; k0 += KCH) {
        __syncthreads();
#pragma unroll
        for (int r = 0; r < 16; r++) {
            int idx = tid + 256 * r;
            Vs[idx] = Vm[(size_t)k0 * DG_ + idx];
        }
        __syncthreads();

#pragma unroll 4
        for (int kk = 0; kk < KCH; kk++) {
            float svl = Ss[pl * 257 + k0 + kk];
            ull sp = pack2(svl, svl);
#pragma unroll
            for (int jj = 0; jj < 8; jj++) {
                float4 v = *(const float4*)&Vs[kk * DG_ + dbase + jj * 4];
                qacc[2 * jj]     = fma2_(sp, pack2(v.x, v.y), qacc[2 * jj]);
                qacc[2 * jj + 1] = fma2_(sp, pack2(v.z, v.w), qacc[2 * jj + 1]);
            }
        }
    }

    float ri = rinvs[pl];
    float* qb = quant_out + ((size_t)n * D_ + (size_t)m * DG_ + dbase) * HW_ + s0 + pl;
#pragma unroll
    for (int jj = 0; jj < 16; jj++) {
        float x, y; unpack2(qacc[jj], x, y);
        qb[(size_t)(2 * jj) * HW_]     = x * ri;
        qb[(size_t)(2 * jj + 1) * HW_] = y * ri;
    }
}

// ---------------------------------------------------------------------------
// Refine: near-exact argmax for flagged near-tie pixels.
// One warp per list entry. 64 blocks x 128 threads.
// ---------------------------------------------------------------------------
__global__ void __launch_bounds__(128)
refine_kernel(const float* __restrict__ latent,
              const float* __restrict__ wq,
              const float* __restrict__ logit_out,
              float* __restrict__ code_out) {
    __shared__ float qv_s[4][DG_];
    __shared__ float qh_s[4][DG_];
    __shared__ float ql_s[4][DG_];

    const int wid  = threadIdx.x >> 5;
    const int lane = threadIdx.x & 31;
    const int gw   = blockIdx.x * 4 + wid;
    const int tw   = gridDim.x * 4;

    int cnt = g_count;
    if (cnt > CAP_) cnt = CAP_;

    for (int e = gw; e < cnt; e += tw) {
        int ent = g_list[e];
        int m = ent & 7;
        int pg = ent >> 3;
        int n = pg >> 10, s = pg & 1023;

        // stage q[d] for this (pixel, m)
        const float* latb = latent + ((size_t)n * D_ + (size_t)m * DG_) * HW_ + s;
        for (int d = lane; d < DG_; d += 32) qv_s[wid][d] = latb[(size_t)d * HW_];
        __syncwarp();

        // qproj in dd: lane handles channels c = lane + 32*ci
        const float* wqm = wq + (size_t)m * DG_ * DG_;
#pragma unroll
        for (int ci = 0; ci < 4; ci++) {
            int c = lane + 32 * ci;
            const float* wr = wqm + (size_t)c * DG_;
            dd a; a.h = 0.f; a.l = 0.f;
            for (int d = 0; d < DG_; d++) a = dd_fma(a, qv_s[wid][d], wr[d]);
            qh_s[wid][c] = a.h; ql_s[wid][c] = a.l;
        }
        __syncwarp();

        // fast logits -> candidate window
        const float* lo = logit_out + ((size_t)pg * M_ + m) * K_;
        float l[8]; float fm = -3.4e38f;
#pragma unroll
        for (int j = 0; j < 8; j++) { l[j] = lo[lane * 8 + j]; fm = fmaxf(fm, l[j]); }
#pragma unroll
        for (int o = 16; o > 0; o >>= 1)
            fm = fmaxf(fm, __shfl_xor_sync(0xFFFFFFFFu, fm, o));
        float thresh = fm - REF_WIN;

        double bestv = -1e300; int besti = 1 << 30;
        const float* kph = g_KPH + ((size_t)m * K_) * DG_;
        const float* kpl = g_KPL + ((size_t)m * K_) * DG_;

#pragma unroll
        for (int j = 0; j < 8; j++) {
            unsigned b = __ballot_sync(0xFFFFFFFFu, l[j] >= thresh);
            while (b) {
                int src = __ffs(b) - 1; b &= b - 1;
                int k = src * 8 + j;
                const float* kh = kph + (size_t)k * DG_;
                const float* kl = kpl + (size_t)k * DG_;
                dd a; a.h = 0.f; a.l = 0.f;
#pragma unroll
                for (int ci = 0; ci < 4; ci++) {
                    int c = lane + 32 * ci;
                    dd kp; kp.h = kh[c]; kp.l = kl[c];
                    dd qp; qp.h = qh_s[wid][c]; qp.l = ql_s[wid][c];
                    a = dd_add(a, dd_mul(kp, qp));
                }
                double v = (double)a.h + (double)a.l;
#pragma unroll
                for (int o = 16; o > 0; o >>= 1)
                    v += __shfl_xor_sync(0xFFFFFFFFu, v, o);
                if (v > bestv || (v == bestv && k < besti)) { bestv = v; besti = k; }
            }
        }
        if (lane == 0) code_out[(size_t)pg * M_ + m] = (float)besti;
    }
}

// ---------------------------------------------------------------------------
extern "C" void kernel_launch(void* const* d_in, const int* in_sizes, int n_in,
                              void* d_out, int out_size) {
    const float* latent   = (const float*)d_in[0];
    const float* codebook = (const float*)d_in[1];
    const float* wq       = (const float*)d_in[2];
    const float* wk       = (const float*)d_in[3];
    const float* wv       = (const float*)d_in[4];
    const float* unif     = (const float*)d_in[5];

    float* out   = (float*)d_out;
    float* quant = out;
    float* code  = out + QUANT_ELEMS;
    float* logit = out + QUANT_ELEMS + CODE_ELEMS;

    precompute_kernel<<<dim3(K_, M_), DG_>>>(codebook, wq, wk, wv);

    cudaFuncSetAttribute(main_kernel,
                         cudaFuncAttributeMaxDynamicSharedMemorySize, SMEM_BYTES);
    main_kernel<<<dim3(NPIX_ / PIX, M_), 256, SMEM_BYTES>>>(
        latent, unif, quant, code, logit);

    refine_kernel<<<64, 128>>>(latent, wq, logit, code);
}

// round 3
// speedup vs baseline: 1.2525x; 1.2525x over previous
#include <cuda_runtime.h>

typedef unsigned long long ull;

#define M_    8
#define K_    256
#define DG_   128
#define D_    1024
#define HW_   1024
#define NPIX_ 32768

#define QUANT_ELEMS (33554432)
#define CODE_ELEMS  (262144)

#define GAP_THRESH 1e-3f
#define REF_WIN    2e-3f
#define CAP_       32768

// Scratch (__device__ globals per allocation rules)
__device__ float g_E[M_ * DG_ * K_];     // [m][d][k]
__device__ float g_V[M_ * K_ * DG_];     // [m][k][d]
__device__ float g_KPH[M_ * K_ * DG_];   // kproj hi [m][k][c]
__device__ float g_KPL[M_ * K_ * DG_];   // kproj lo
__device__ int   g_count;
__device__ int   g_list[CAP_];

// ---------------- packed f32x2 helpers ----------------
__device__ __forceinline__ ull pack2(float x, float y) {
    ull r; asm("mov.b64 %0, {%1,%2};" : "=l"(r) : "f"(x), "f"(y)); return r;
}
__device__ __forceinline__ void unpack2(ull v, float &x, float &y) {
    asm("mov.b64 {%0,%1}, %2;" : "=f"(x), "=f"(y) : "l"(v));
}
__device__ __forceinline__ ull fma2_(ull a, ull b, ull c) {
    ull d; asm("fma.rn.f32x2 %0, %1, %2, %3;" : "=l"(d) : "l"(a), "l"(b), "l"(c));
    return d;
}

// ---------------- double-float (Dekker) helpers: fast-math safe ----------------
struct dd { float h, l; };

__device__ __forceinline__ dd two_sum(float a, float b) {
    float s  = __fadd_rn(a, b);
    float bb = __fsub_rn(s, a);
    float e  = __fadd_rn(__fsub_rn(a, __fsub_rn(s, bb)), __fsub_rn(b, bb));
    dd r; r.h = s; r.l = e; return r;
}
__device__ __forceinline__ dd two_prod(float a, float b) {
    float p = __fmul_rn(a, b);
    float e = __fmaf_rn(a, b, -p);
    dd r; r.h = p; r.l = e; return r;
}
__device__ __forceinline__ dd dd_add(dd x, dd y) {
    dd s = two_sum(x.h, y.h);
    float lo = __fadd_rn(__fadd_rn(x.l, y.l), s.l);
    float hi = __fadd_rn(s.h, lo);
    float l  = __fadd_rn(__fsub_rn(s.h, hi), lo);
    dd r; r.h = hi; r.l = l; return r;
}
__device__ __forceinline__ dd dd_fma(dd acc, float a, float b) {
    return dd_add(acc, two_prod(a, b));
}
__device__ __forceinline__ dd dd_mul(dd x, dd y) {
    dd p = two_prod(x.h, y.h);
    float t = __fmaf_rn(x.h, y.l, p.l);
    t = __fmaf_rn(x.l, y.h, t);
    float hi = __fadd_rn(p.h, t);
    float l  = __fadd_rn(__fsub_rn(p.h, hi), t);
    dd r; r.h = hi; r.l = l; return r;
}

// ---------------------------------------------------------------------------
// Precompute (rewritten): grid (K_/8 = 32, M_), 256 threads.
// Per block: 8 k values of one m.
//   Phase A: kproj (dd) + vproj (fp32) via smem-staged wk/wv chunks.
//   Phase B: E[d][k] = sum_c kph[k][c] * wq[c][d] via smem-staged wq chunks.
// ---------------------------------------------------------------------------
#define PRE_SM_CB   0                      // [8][128]        = 1024
#define PRE_SM_KP   1024                   // [8][128]        = 1024
#define PRE_SM_WK   2048                   // [128][33]       = 4224
#define PRE_SM_WV   (2048 + 4224)          // [128][33]       = 4224
#define PRE_SM_WQ   2048                   // [32][128]       = 4096 (reuses WK region)
#define PRE_SM_FLOATS (2048 + 4224 + 4224)

__global__ void __launch_bounds__(256)
precompute_kernel(const float* __restrict__ codebook,
                  const float* __restrict__ wq,
                  const float* __restrict__ wk,
                  const float* __restrict__ wv) {
    __shared__ float sm[PRE_SM_FLOATS];
    float* cbs = sm + PRE_SM_CB;
    float* kps = sm + PRE_SM_KP;
    float* wks = sm + PRE_SM_WK;
    float* wvs = sm + PRE_SM_WV;
    float* wqs = sm + PRE_SM_WQ;

    const int m  = blockIdx.y;
    const int k0 = blockIdx.x * 8;
    const int tid   = threadIdx.x;
    const int c     = tid & 127;       // phase A: channel ; phase B: d
    const int khalf = tid >> 7;        // 0/1 -> kk in {khalf*4 .. +3}

    if (m == 0 && blockIdx.x == 0 && tid == 0) g_count = 0;

    // stage cb[8][128] (contiguous in codebook)
#pragma unroll
    for (int r = 0; r < 4; r++) {
        int idx = tid + 256 * r;
        cbs[idx] = codebook[((size_t)m * K_ + k0) * DG_ + idx];
    }

    // ---------- Phase A: kproj (dd) / vproj ----------
    dd  sk[4];
    float sv[4];
#pragma unroll
    for (int i = 0; i < 4; i++) { sk[i].h = 0.f; sk[i].l = 0.f; sv[i] = 0.f; }

    const float* wkm = wk + (size_t)m * DG_ * DG_;
    const float* wvm = wv + (size_t)m * DG_ * DG_;

    for (int dc = 0; dc < DG_; dc += 32) {
        __syncthreads();
        // stage wk/wv chunk [128 c][32 d], padded stride 33
#pragma unroll
        for (int r = 0; r < 16; r++) {
            int idx = tid + 256 * r;
            int cc = idx >> 5, j = idx & 31;
            wks[cc * 33 + j] = wkm[(size_t)cc * DG_ + dc + j];
            wvs[cc * 33 + j] = wvm[(size_t)cc * DG_ + dc + j];
        }
        __syncthreads();

#pragma unroll 4
        for (int j = 0; j < 32; j++) {
            float wkv = wks[c * 33 + j];
            float wvv = wvs[c * 33 + j];
#pragma unroll
            for (int i = 0; i < 4; i++) {
                float cbv = cbs[(khalf * 4 + i) * DG_ + dc + j];
                sk[i] = dd_fma(sk[i], cbv, wkv);
                sv[i] = fmaf(cbv, wvv, sv[i]);
            }
        }
    }

#pragma unroll
    for (int i = 0; i < 4; i++) {
        int kk = khalf * 4 + i;
        size_t gb = ((size_t)m * K_ + k0 + kk) * DG_ + c;
        g_KPH[gb] = sk[i].h;
        g_KPL[gb] = sk[i].l;
        g_V[gb]   = sv[i];
        kps[kk * DG_ + c] = sk[i].h;
    }

    // ---------- Phase B: E[d][k] ----------
    const int d = c;   // thread's output row
    float ea[4];
#pragma unroll
    for (int i = 0; i < 4; i++) ea[i] = 0.f;

    const float* wqm = wq + (size_t)m * DG_ * DG_;
    for (int c0 = 0; c0 < DG_; c0 += 32) {
        __syncthreads();
        // stage wq chunk [32 c][128 d] (row-contiguous, no pad needed)
#pragma unroll
        for (int r = 0; r < 16; r++) {
            int idx = tid + 256 * r;
            wqs[idx] = wqm[(size_t)c0 * DG_ + idx];
        }
        __syncthreads();

#pragma unroll 4
        for (int cc = 0; cc < 32; cc++) {
            float wv_ = wqs[cc * DG_ + d];     // lane-stride 1, conflict-free
#pragma unroll
            for (int i = 0; i < 4; i++)
                ea[i] = fmaf(kps[(khalf * 4 + i) * DG_ + c0 + cc], wv_, ea[i]);
        }
    }

#pragma unroll
    for (int i = 0; i < 4; i++)
        g_E[((size_t)m * DG_ + d) * K_ + k0 + khalf * 4 + i] = ea[i];
}

// ---------------------------------------------------------------------------
// Main kernel: block = 256 threads, tile = 64 pixels x 256 k, fixed m.
// grid (NPIX_/64 = 512, M_ = 8)
// Thread kt owns k in {kt*4..kt*4+3} and {128+kt*4..+3}  (conflict-free LDS)
// ---------------------------------------------------------------------------
#define PIX  64
#define DCH  16
#define KCH  32

#define SM_QS    0
#define SM_ES    1024
#define SM_SS    5120
#define SM_RINV  (5120 + 16448)
#define SM_VS    (5120 + 16448 + 64)
#define SM_FLOATS (5120 + 16448 + 64 + 4096)
#define SMEM_BYTES (SM_FLOATS * 4)

__global__ void __launch_bounds__(256, 2)
main_kernel(const float* __restrict__ latent,
            const float* __restrict__ unif,
            float* __restrict__ quant_out,
            float* __restrict__ code_out,
            float* __restrict__ logit_out) {
    extern __shared__ float sm[];
    float* Qs    = sm + SM_QS;
    float* Es    = sm + SM_ES;
    float* Ss    = sm + SM_SS;
    float* rinvs = sm + SM_RINV;
    float* Vs    = sm + SM_VS;

    const int m  = blockIdx.y;
    const int p0 = blockIdx.x * PIX;
    const int n  = p0 >> 10;
    const int s0 = p0 & 1023;
    const int tid = threadIdx.x;
    const int kt  = tid & 31;
    const int pt  = tid >> 5;

    const float* latb = latent + ((size_t)n * D_ + (size_t)m * DG_) * HW_ + s0;
    const float* Em   = g_E + (size_t)m * DG_ * K_;

    // ---------------- Pass 1: logits ----------------
    ull acc[8][4];
#pragma unroll
    for (int i = 0; i < 8; i++)
#pragma unroll
        for (int jj = 0; jj < 4; jj++) acc[i][jj] = 0ull;

    for (int d0 = 0; d0 < DG_; d0 += DCH) {
#pragma unroll
        for (int r = 0; r < 4; r++) {
            int idx = tid + 256 * r;
            int dr = idx >> 6, cc = idx & 63;
            Qs[idx] = latb[(size_t)(d0 + dr) * HW_ + cc];
        }
#pragma unroll
        for (int r = 0; r < 16; r++) {
            int idx = tid + 256 * r;
            Es[idx] = Em[(size_t)d0 * K_ + idx];
        }
        __syncthreads();

#pragma unroll
        for (int d = 0; d < DCH; d++) {
            // k = kt*4..+3 (low half) and 128+kt*4..+3 (high half): 16B lane
            // stride -> each LDS.128 phase covers exactly 128B, conflict-free.
            float4 e0 = *(const float4*)&Es[d * K_ + kt * 4];
            float4 e1 = *(const float4*)&Es[d * K_ + 128 + kt * 4];
            ull eb[4];
            eb[0] = pack2(e0.x, e0.y); eb[1] = pack2(e0.z, e0.w);
            eb[2] = pack2(e1.x, e1.y); eb[3] = pack2(e1.z, e1.w);
            float4 q0 = *(const float4*)&Qs[d * PIX + pt * 8];      // warp broadcast
            float4 q1 = *(const float4*)&Qs[d * PIX + pt * 8 + 4];  // warp broadcast
            float qv[8] = {q0.x, q0.y, q0.z, q0.w, q1.x, q1.y, q1.z, q1.w};
#pragma unroll
            for (int i = 0; i < 8; i++) {
                ull qd = pack2(qv[i], qv[i]);
#pragma unroll
                for (int jj = 0; jj < 4; jj++)
                    acc[i][jj] = fma2_(qd, eb[jj], acc[i][jj]);
            }
        }
        __syncthreads();
    }

    // ---------------- Epilogue ----------------
#pragma unroll 2
    for (int i = 0; i < 8; i++) {
        const int p = pt * 8 + i;
        const size_t pg = (size_t)(p0 + p);

        float l[8];     // l[0..3] -> k = kt*4+j ; l[4..7] -> k = 128+kt*4+(j-4)
#pragma unroll
        for (int jj = 0; jj < 4; jj++) unpack2(acc[i][jj], l[2 * jj], l[2 * jj + 1]);

        float* lo = logit_out + (pg * M_ + m) * K_;
        *(float4*)(lo + kt * 4)       = make_float4(l[0], l[1], l[2], l[3]);
        *(float4*)(lo + 128 + kt * 4) = make_float4(l[4], l[5], l[6], l[7]);

        // top-2 of raw logits (first-index tie break on top-1)
        float b1 = l[0]; int i1 = kt * 4; float b2 = -3.4e38f;
#pragma unroll
        for (int j = 1; j < 8; j++) {
            int kj = (j < 4) ? (kt * 4 + j) : (128 + kt * 4 + j - 4);
            if (l[j] > b1 || (l[j] == b1 && kj < i1)) { b2 = b1; b1 = l[j]; i1 = kj; }
            else if (l[j] > b2) b2 = l[j];
        }
#pragma unroll
        for (int o = 16; o > 0; o >>= 1) {
            float ob1 = __shfl_xor_sync(0xFFFFFFFFu, b1, o);
            int   oi1 = __shfl_xor_sync(0xFFFFFFFFu, i1, o);
            float ob2 = __shfl_xor_sync(0xFFFFFFFFu, b2, o);
            if (ob1 > b1 || (ob1 == b1 && oi1 < i1)) {
                b2 = fmaxf(b1, ob2); b1 = ob1; i1 = oi1;
            } else {
                b2 = fmaxf(b2, ob1);
            }
        }

        // gumbel: -log(-log u); inner log via log1pf (accurate at u->1)
        const float* up = unif + (pg * M_ + m) * K_;
        float4 u0 = *(const float4*)(up + kt * 4);
        float4 u1 = *(const float4*)(up + 128 + kt * 4);
        float uu[8] = {u0.x, u0.y, u0.z, u0.w, u1.x, u1.y, u1.z, u1.w};
        float t[8];
#pragma unroll
        for (int j = 0; j < 8; j++) {
            float nlu = -log1pf(__fsub_rn(uu[j], 1.0f));
            t[j] = l[j] - __logf(nlu);
        }

        float tm = t[0];
#pragma unroll
        for (int j = 1; j < 8; j++) tm = fmaxf(tm, t[j]);
#pragma unroll
        for (int o = 16; o > 0; o >>= 1)
            tm = fmaxf(tm, __shfl_xor_sync(0xFFFFFFFFu, tm, o));

        float e[8], s = 0.f;
#pragma unroll
        for (int j = 0; j < 8; j++) { e[j] = __expf(t[j] - tm); s += e[j]; }
#pragma unroll
        for (int o = 16; o > 0; o >>= 1)
            s += __shfl_xor_sync(0xFFFFFFFFu, s, o);

#pragma unroll
        for (int j = 0; j < 4; j++) Ss[p * 257 + kt * 4 + j] = e[j];
#pragma unroll
        for (int j = 4; j < 8; j++) Ss[p * 257 + 128 + kt * 4 + j - 4] = e[j];
        if (kt == 0) {
            rinvs[p] = 1.0f / s;
            code_out[pg * M_ + m] = (float)i1;
            if (b1 - b2 < GAP_THRESH) {
                int idx = atomicAdd(&g_count, 1);
                if (idx < CAP_) g_list[idx] = (int)(pg * M_ + m);
            }
        }
    }

    // ---------------- Pass 2: quantized ----------------
    const int pl    = tid & 63;
    const int dbase = (tid >> 6) * 32;

    ull qacc[16];
#pragma unroll
    for (int jj = 0; jj < 16; jj++) qacc[jj] = 0ull;

    const float* Vm = g_V + (size_t)m * K_ * DG_;
    for (int k0 = 0; k0 < K_; k0 += KCH) {
        __syncthreads();
#pragma unroll
        for (int r = 0; r < 16; r++) {
            int idx = tid + 256 * r;
            Vs[idx] = Vm[(size_t)k0 * DG_ + idx];
        }
        __syncthreads();

#pragma unroll 4
        for (int kk = 0; kk < KCH; kk++) {
            float svl = Ss[pl * 257 + k0 + kk];
            ull sp = pack2(svl, svl);
#pragma unroll
            for (int jj = 0; jj < 8; jj++) {
                float4 v = *(const float4*)&Vs[kk * DG_ + dbase + jj * 4];
                qacc[2 * jj]     = fma2_(sp, pack2(v.x, v.y), qacc[2 * jj]);
                qacc[2 * jj + 1] = fma2_(sp, pack2(v.z, v.w), qacc[2 * jj + 1]);
            }
        }
    }

    float ri = rinvs[pl];
    float* qb = quant_out + ((size_t)n * D_ + (size_t)m * DG_ + dbase) * HW_ + s0 + pl;
#pragma unroll
    for (int jj = 0; jj < 16; jj++) {
        float x, y; unpack2(qacc[jj], x, y);
        qb[(size_t)(2 * jj) * HW_]     = x * ri;
        qb[(size_t)(2 * jj + 1) * HW_] = y * ri;
    }
}

// ---------------------------------------------------------------------------
// Refine: near-exact argmax for flagged near-tie pixels. One warp per entry.
// ---------------------------------------------------------------------------
__global__ void __launch_bounds__(128)
refine_kernel(const float* __restrict__ latent,
              const float* __restrict__ wq,
              const float* __restrict__ logit_out,
              float* __restrict__ code_out) {
    __shared__ float qv_s[4][DG_];
    __shared__ float qh_s[4][DG_];
    __shared__ float ql_s[4][DG_];

    const int wid  = threadIdx.x >> 5;
    const int lane = threadIdx.x & 31;
    const int gw   = blockIdx.x * 4 + wid;
    const int tw   = gridDim.x * 4;

    int cnt = g_count;
    if (cnt > CAP_) cnt = CAP_;

    for (int e = gw; e < cnt; e += tw) {
        int ent = g_list[e];
        int m = ent & 7;
        int pg = ent >> 3;
        int n = pg >> 10, s = pg & 1023;

        const float* latb = latent + ((size_t)n * D_ + (size_t)m * DG_) * HW_ + s;
        for (int d = lane; d < DG_; d += 32) qv_s[wid][d] = latb[(size_t)d * HW_];
        __syncwarp();

        const float* wqm = wq + (size_t)m * DG_ * DG_;
#pragma unroll
        for (int ci = 0; ci < 4; ci++) {
            int c = lane + 32 * ci;
            const float* wr = wqm + (size_t)c * DG_;
            dd a; a.h = 0.f; a.l = 0.f;
            for (int d = 0; d < DG_; d++) a = dd_fma(a, qv_s[wid][d], wr[d]);
            qh_s[wid][c] = a.h; ql_s[wid][c] = a.l;
        }
        __syncwarp();

        const float* lo = logit_out + ((size_t)pg * M_ + m) * K_;
        float l[8]; float fm = -3.4e38f;
#pragma unroll
        for (int j = 0; j < 8; j++) { l[j] = lo[lane * 8 + j]; fm = fmaxf(fm, l[j]); }
#pragma unroll
        for (int o = 16; o > 0; o >>= 1)
            fm = fmaxf(fm, __shfl_xor_sync(0xFFFFFFFFu, fm, o));
        float thresh = fm - REF_WIN;

        double bestv = -1e300; int besti = 1 << 30;
        const float* kph = g_KPH + ((size_t)m * K_) * DG_;
        const float* kpl = g_KPL + ((size_t)m * K_) * DG_;

#pragma unroll
        for (int j = 0; j < 8; j++) {
            unsigned b = __ballot_sync(0xFFFFFFFFu, l[j] >= thresh);
            while (b) {
                int src = __ffs(b) - 1; b &= b - 1;
                int k = src * 8 + j;
                const float* kh = kph + (size_t)k * DG_;
                const float* kl = kpl + (size_t)k * DG_;
                dd a; a.h = 0.f; a.l = 0.f;
#pragma unroll
                for (int ci = 0; ci < 4; ci++) {
                    int c = lane + 32 * ci;
                    dd kp; kp.h = kh[c]; kp.l = kl[c];
                    dd qp; qp.h = qh_s[wid][c]; qp.l = ql_s[wid][c];
                    a = dd_add(a, dd_mul(kp, qp));
                }
                double v = (double)a.h + (double)a.l;
#pragma unroll
                for (int o = 16; o > 0; o >>= 1)
                    v += __shfl_xor_sync(0xFFFFFFFFu, v, o);
                if (v > bestv || (v == bestv && k < besti)) { bestv = v; besti = k; }
            }
        }
        if (lane == 0) code_out[(size_t)pg * M_ + m] = (float)besti;
    }
}

// ---------------------------------------------------------------------------
extern "C" void kernel_launch(void* const* d_in, const int* in_sizes, int n_in,
                              void* d_out, int out_size) {
    const float* latent   = (const float*)d_in[0];
    const float* codebook = (const float*)d_in[1];
    const float* wq       = (const float*)d_in[2];
    const float* wk       = (const float*)d_in[3];
    const float* wv       = (const float*)d_in[4];
    const float* unif     = (const float*)d_in[5];

    float* out   = (float*)d_out;
    float* quant = out;
    float* code  = out + QUANT_ELEMS;
    float* logit = out + QUANT_ELEMS + CODE_ELEMS;

    precompute_kernel<<<dim3(K_ / 8, M_), 256>>>(codebook, wq, wk, wv);

    cudaFuncSetAttribute(main_kernel,
                         cudaFuncAttributeMaxDynamicSharedMemorySize, SMEM_BYTES);
    main_kernel<<<dim3(NPIX_ / PIX, M_), 256, SMEM_BYTES>>>(
        latent, unif, quant, code, logit);

    refine_kernel<<<64, 128>>>(latent, wq, logit, code);
}